// round 15
// baseline (speedup 1.0000x reference)
#include <cuda_runtime.h>
#include <cuda_bf16.h>
#include <cstdint>

#define NN 100000
#define DH 128
#define NE 1600000
#define BN_EPS 1e-5f
#define SLOTS 48
#define OVF_CAP 8192

// ---------------- scratch (device globals; no allocation allowed) ----------------
__device__ __align__(128) float g_buf[NN * DH];
__device__ __align__(128) float g_agg[NN * DH];
__device__ __align__(128) int   g_slot[NN * SLOTS];
__device__ int   g_pos[NN];
__device__ int   g_outdeg[NN];
__device__ float g_norm_src[NN];
__device__ float g_norm_dst[NN];
__device__ float g_colsum[DH];
__device__ float g_colsq[DH];
__device__ float g_scale[DH];
__device__ float g_shift[DH];
__device__ int   g_ovf[OVF_CAP];
__device__ int   g_n_ovf;

// ---------------- small utility kernels ----------------
__global__ void k_zero() {
    int i = blockIdx.x * blockDim.x + threadIdx.x;
    if (i < NN) { g_outdeg[i] = 0; g_pos[i] = 0; }
    if (i < DH) { g_colsum[i] = 0.f; g_colsq[i] = 0.f; }
    if (i == 0) g_n_ovf = 0;
}

__global__ void k_build(const int* __restrict__ src, const int* __restrict__ dst) {
    int e = blockIdx.x * blockDim.x + threadIdx.x;
    if (e >= NE) return;
    int s = src[e];
    int d = dst[e];
    atomicAdd(&g_outdeg[s], 1);
    int p = atomicAdd(&g_pos[d], 1);
    if (p < SLOTS) {
        g_slot[d * SLOTS + p] = s;
    } else {
        int o = atomicAdd(&g_n_ovf, 1);
        if (o < OVF_CAP) g_ovf[o] = e;
    }
}

__global__ void k_norms() {
    int i = blockIdx.x * blockDim.x + threadIdx.x;
    if (i < NN) {
        g_norm_src[i] = rsqrtf(fmaxf((float)g_outdeg[i], 1.0f));
        g_norm_dst[i] = rsqrtf(fmaxf((float)g_pos[i], 1.0f));
    }
}

__global__ void k_colreduce() {
    int c = threadIdx.x;  // 128 threads
    float s = 0.f, sq = 0.f;
    for (int r = blockIdx.x; r < NN; r += gridDim.x) {
        float v = g_buf[r * DH + c];
        s += v;
        sq += v * v;
    }
    atomicAdd(&g_colsum[c], s);
    atomicAdd(&g_colsq[c], sq);
}

__global__ void k_bnfin(const float* __restrict__ gamma, const float* __restrict__ beta) {
    int c = threadIdx.x;
    float mu  = g_colsum[c] * (1.0f / NN);
    float var = g_colsq[c] * (1.0f / NN) - mu * mu;
    float inv = rsqrtf(var + BN_EPS);
    float sc  = gamma[c] * inv;
    g_scale[c] = sc;
    g_shift[c] = beta[c] - mu * sc;
}

// ---------------- gather (unchanged) ----------------
__global__ void __launch_bounds__(256) k_gather() {
    int warp = (blockIdx.x * blockDim.x + threadIdx.x) >> 5;
    int lane = threadIdx.x & 31;
    if (warp >= NN) return;
    int n = g_pos[warp];
    if (n > SLOTS) n = SLOTS;
    const int* sl = &g_slot[warp * SLOTS];
    const float* bufl = g_buf + (lane * 4);
    float4 acc = make_float4(0.f, 0.f, 0.f, 0.f);
    int s_next = (n > 0) ? __ldg(&sl[0]) : 0;
    for (int j = 0; j < n; j++) {
        int s = s_next;
        if (j + 1 < n) s_next = __ldg(&sl[j + 1]);
        float4 v = *(const float4*)(bufl + s * DH);
        acc.x += v.x; acc.y += v.y; acc.z += v.z; acc.w += v.w;
    }
    *(float4*)&g_agg[warp * DH + lane * 4] = acc;
}

__global__ void k_ovf(const int* __restrict__ src, const int* __restrict__ dst) {
    int n = g_n_ovf;
    if (n > OVF_CAP) n = OVF_CAP;
    int warp = threadIdx.x >> 5;
    int lane = threadIdx.x & 31;
    int loff = lane * 4;
    for (int i = warp; i < n; i += 8) {
        int e = g_ovf[i];
        int s = __ldg(&src[e]);
        int d = __ldg(&dst[e]);
        float4 v = *(const float4*)&g_buf[s * DH + loff];
        float* p = &g_agg[d * DH + loff];
        asm volatile("red.global.add.v4.f32 [%0], {%1, %2, %3, %4};"
                     :: "l"(p), "f"(v.x), "f"(v.y), "f"(v.z), "f"(v.w)
                     : "memory");
    }
}

// ---------------- helpers ----------------
__device__ __forceinline__ uint32_t pack_bf2(__nv_bfloat16 lo16, __nv_bfloat16 hi16) {
    __nv_bfloat162 t; t.x = lo16; t.y = hi16;  // .x at lower address / low 16 bits
    uint32_t u; *(__nv_bfloat162*)&u = t; return u;
}

__device__ __forceinline__ void mma_bf16(float* c, const uint32_t* a, uint32_t b0, uint32_t b1) {
    asm volatile(
        "mma.sync.aligned.m16n8k16.row.col.f32.bf16.bf16.f32 "
        "{%0,%1,%2,%3}, {%4,%5,%6,%7}, {%8,%9}, {%0,%1,%2,%3};"
        : "+f"(c[0]), "+f"(c[1]), "+f"(c[2]), "+f"(c[3])
        : "r"(a[0]), "r"(a[1]), "r"(a[2]), "r"(a[3]), "r"(b0), "r"(b1));
}

// ---------------- tensor-core GEMM (mma.sync bf16, hi/lo 3-pass split) ----------------
// Block: 128 rows x 128 cols, 256 threads = 8 warps as 4(row-groups of 32) x 2(col-groups of 64).
// Warp tile: 32x64 = 2 m16-tiles x 8 n8-tiles. K processed in 4 smem chunks of 32.
// B[n][k] = W[k][n] (transposed into smem, k-contiguous) -> .row.col fragments are plain b32 LDS.
// MODE 0: A=in_feat;  out = acc + bias                      -> g_buf
// MODE 1: A=relu(g_buf*scale_k+shift_k); out=relu(acc+bias)*norm_src -> g_buf (in-place: block
//         reads only its own 128 rows during k-loop, writes them in epilogue after last sync)
// MODE 2: A=g_agg; out = relu(acc*norm_dst + bias)*norm_src -> g_buf
// MODE 3: A=g_agg; out = acc*norm_dst + bias                -> d_out
template <int MODE>
__global__ void __launch_bounds__(256) k_tc(const float* __restrict__ Ain,
                                            const float* __restrict__ W,
                                            const float* __restrict__ bias,
                                            float* __restrict__ Oout) {
    __shared__ __nv_bfloat16 Ahi[128][40];  // [row][k], pad 40 -> conflict-free frag LDS
    __shared__ __nv_bfloat16 Alo[128][40];
    __shared__ __nv_bfloat16 Bhi[128][40];  // [n][k]
    __shared__ __nv_bfloat16 Blo[128][40];

    const float* A = (MODE == 0) ? Ain : (MODE == 1 ? g_buf : g_agg);
    float* O       = (MODE == 3) ? Oout : g_buf;

    int tid    = threadIdx.x;
    int wid    = tid >> 5;
    int lane   = tid & 31;
    int gid    = lane >> 2;   // 0..7
    int tid4   = lane & 3;    // 0..3
    int warp_r = wid >> 1;    // 0..3 -> rows warp_r*32
    int warp_c = wid & 1;     // 0..1 -> cols warp_c*64
    int row0   = blockIdx.x * 128;

    float acc[2][8][4];
#pragma unroll
    for (int mt = 0; mt < 2; mt++)
#pragma unroll
        for (int nt = 0; nt < 8; nt++)
#pragma unroll
            for (int j = 0; j < 4; j++) acc[mt][nt][j] = 0.f;

    for (int kc = 0; kc < DH; kc += 32) {
        // ---- A tile: 128 rows x 32 k as float4 (1024 loads / 4 per thread) ----
#pragma unroll
        for (int t = 0; t < 4; t++) {
            int f  = t * 256 + tid;
            int r  = f >> 3;          // 0..127
            int k4 = f & 7;           // float4 index; k = k4*4
            int gr = row0 + r;
            float4 x = (gr < NN) ? *(const float4*)&A[(size_t)gr * DH + kc + k4 * 4]
                                 : make_float4(0.f, 0.f, 0.f, 0.f);
            if (MODE == 1) {
                float4 sc = *(const float4*)&g_scale[kc + k4 * 4];
                float4 sh = *(const float4*)&g_shift[kc + k4 * 4];
                x.x = fmaxf(fmaf(x.x, sc.x, sh.x), 0.f);
                x.y = fmaxf(fmaf(x.y, sc.y, sh.y), 0.f);
                x.z = fmaxf(fmaf(x.z, sc.z, sh.z), 0.f);
                x.w = fmaxf(fmaf(x.w, sc.w, sh.w), 0.f);
            }
            __nv_bfloat16 h0 = __float2bfloat16(x.x), h1 = __float2bfloat16(x.y);
            __nv_bfloat16 h2 = __float2bfloat16(x.z), h3 = __float2bfloat16(x.w);
            __nv_bfloat16 l0 = __float2bfloat16(x.x - __bfloat162float(h0));
            __nv_bfloat16 l1 = __float2bfloat16(x.y - __bfloat162float(h1));
            __nv_bfloat16 l2 = __float2bfloat16(x.z - __bfloat162float(h2));
            __nv_bfloat16 l3 = __float2bfloat16(x.w - __bfloat162float(h3));
            int k = k4 * 4;
            *(uint32_t*)&Ahi[r][k]     = pack_bf2(h0, h1);
            *(uint32_t*)&Ahi[r][k + 2] = pack_bf2(h2, h3);
            *(uint32_t*)&Alo[r][k]     = pack_bf2(l0, l1);
            *(uint32_t*)&Alo[r][k + 2] = pack_bf2(l2, l3);
        }
        // ---- B tile: Bs[n][kl] = W[kc+kl][n], 32 kl x 128 n (scalar, coalesced reads) ----
#pragma unroll
        for (int t = 0; t < 16; t++) {
            int f  = t * 256 + tid;
            int kl = f >> 7;          // 0..31
            int n  = f & 127;
            float w = W[(size_t)(kc + kl) * DH + n];
            __nv_bfloat16 h = __float2bfloat16(w);
            __nv_bfloat16 l = __float2bfloat16(w - __bfloat162float(h));
            Bhi[n][kl] = h;
            Blo[n][kl] = l;
        }
        __syncthreads();

#pragma unroll
        for (int ks = 0; ks < 32; ks += 16) {
            int ka = ks + tid4 * 2;
            uint32_t a_hi[2][4], a_lo[2][4];
#pragma unroll
            for (int mt = 0; mt < 2; mt++) {
                int r0 = warp_r * 32 + mt * 16 + gid;
                a_hi[mt][0] = *(const uint32_t*)&Ahi[r0][ka];
                a_hi[mt][1] = *(const uint32_t*)&Ahi[r0 + 8][ka];
                a_hi[mt][2] = *(const uint32_t*)&Ahi[r0][ka + 8];
                a_hi[mt][3] = *(const uint32_t*)&Ahi[r0 + 8][ka + 8];
                a_lo[mt][0] = *(const uint32_t*)&Alo[r0][ka];
                a_lo[mt][1] = *(const uint32_t*)&Alo[r0 + 8][ka];
                a_lo[mt][2] = *(const uint32_t*)&Alo[r0][ka + 8];
                a_lo[mt][3] = *(const uint32_t*)&Alo[r0 + 8][ka + 8];
            }
#pragma unroll
            for (int nt = 0; nt < 8; nt++) {
                int nb = warp_c * 64 + nt * 8 + gid;
                uint32_t bh0 = *(const uint32_t*)&Bhi[nb][ka];
                uint32_t bh1 = *(const uint32_t*)&Bhi[nb][ka + 8];
                uint32_t bl0 = *(const uint32_t*)&Blo[nb][ka];
                uint32_t bl1 = *(const uint32_t*)&Blo[nb][ka + 8];
#pragma unroll
                for (int mt = 0; mt < 2; mt++) {
                    mma_bf16(acc[mt][nt], a_hi[mt], bh0, bh1);  // hi*hi
                    mma_bf16(acc[mt][nt], a_hi[mt], bl0, bl1);  // hi*lo
                    mma_bf16(acc[mt][nt], a_lo[mt], bh0, bh1);  // lo*hi
                }
            }
        }
        __syncthreads();
    }

    // ---- epilogue ----
#pragma unroll
    for (int mt = 0; mt < 2; mt++) {
        int r0 = row0 + warp_r * 32 + mt * 16 + gid;  // rows r0 and r0+8
#pragma unroll
        for (int nt = 0; nt < 8; nt++) {
            int col = warp_c * 64 + nt * 8 + tid4 * 2;
            float2 bv = *(const float2*)&bias[col];
            float* a = acc[mt][nt];
#pragma unroll
            for (int half = 0; half < 2; half++) {
                int r = r0 + half * 8;
                if (r >= NN) continue;
                float vx = a[half * 2 + 0];
                float vy = a[half * 2 + 1];
                if (MODE == 0) {
                    vx += bv.x; vy += bv.y;
                } else if (MODE == 1) {
                    float ns = g_norm_src[r];
                    vx = fmaxf(vx + bv.x, 0.f) * ns;
                    vy = fmaxf(vy + bv.y, 0.f) * ns;
                } else if (MODE == 2) {
                    float nd = g_norm_dst[r];
                    float ns = g_norm_src[r];
                    vx = fmaxf(fmaf(vx, nd, bv.x), 0.f) * ns;
                    vy = fmaxf(fmaf(vy, nd, bv.y), 0.f) * ns;
                } else {
                    float nd = g_norm_dst[r];
                    vx = fmaf(vx, nd, bv.x);
                    vy = fmaf(vy, nd, bv.y);
                }
                float2 v = make_float2(vx, vy);
                *(float2*)&O[(size_t)r * DH + col] = v;
            }
        }
    }
}

// ---------------- launch ----------------
extern "C" void kernel_launch(void* const* d_in, const int* in_sizes, int n_in,
                              void* d_out, int out_size) {
    const float* in_feat = (const float*)d_in[0];
    const int*   src     = (const int*)d_in[1];
    const int*   dst     = (const int*)d_in[2];
    const float* W1      = (const float*)d_in[3];
    const float* b1      = (const float*)d_in[4];
    const float* gamma   = (const float*)d_in[5];
    const float* beta    = (const float*)d_in[6];
    const float* W2      = (const float*)d_in[7];
    const float* b2      = (const float*)d_in[8];
    const float* Wc      = (const float*)d_in[9];
    const float* bc      = (const float*)d_in[10];
    float* out = (float*)d_out;

    const int GEMM_GRID   = (NN + 127) / 128;  // 782
    const int GATHER_GRID = (NN + 7) / 8;      // 12500

    k_zero<<<(NN + 255) / 256, 256>>>();
    k_build<<<(NE + 255) / 256, 256>>>(src, dst);
    k_norms<<<(NN + 255) / 256, 256>>>();

    // MLP
    k_tc<0><<<GEMM_GRID, 256>>>(in_feat, W1, b1, nullptr);
    k_colreduce<<<512, DH>>>();
    k_bnfin<<<1, DH>>>(gamma, beta);
    k_tc<1><<<GEMM_GRID, 256>>>(nullptr, W2, b2, nullptr);

    // 3 propagation steps
    for (int s = 0; s < 3; s++) {
        k_gather<<<GATHER_GRID, 256>>>();
        k_ovf<<<1, 256>>>(src, dst);
        if (s < 2)
            k_tc<2><<<GEMM_GRID, 256>>>(nullptr, Wc, bc, nullptr);
        else
            k_tc<3><<<GEMM_GRID, 256>>>(nullptr, Wc, bc, out);
    }
}